// round 2
// baseline (speedup 1.0000x reference)
#include <cuda_runtime.h>
#include <math.h>
#include <stdint.h>

#define NBATCH 2
#define CDIM 320
#define NTOK 16384
#define DIN 1352
#define DINNER 640
#define CONVD 704
#define DSTATE 32
#define NH 8
#define HP 80
#define NCHUNK 256
#define INNERD 160
#define MLPD 1024

// ------------------------------ arena ------------------------------
constexpr size_t SZ_XF   = (size_t)NBATCH*NTOK*CDIM;      // 10.5M
constexpr size_t SZ_ZX   = (size_t)NBATCH*NTOK*DIN;       // 44.3M
constexpr size_t SZ_XBC  = (size_t)NBATCH*NTOK*CONVD;     // 23.1M
constexpr size_t SZ_DTB  = (size_t)NBATCH*NH*NTOK;        // (b,h,t)
constexpr size_t SZ_SL   = (size_t)NBATCH*NH*NCHUNK*DSTATE*HP;
constexpr size_t SZ_Y    = (size_t)NBATCH*NTOK*DINNER;
constexpr size_t SZ_KPE  = (size_t)NTOK*CDIM;
constexpr size_t SZ_I160 = (size_t)NBATCH*NTOK*INNERD;
constexpr size_t SZ_ATT  = (size_t)48*NTOK;

constexpr size_t OFF_XF    = 0;
constexpr size_t OFF_XN    = OFF_XF    + SZ_XF;
constexpr size_t OFF_ZX    = OFF_XN    + SZ_XF;
constexpr size_t OFF_XBC   = OFF_ZX    + SZ_ZX;
constexpr size_t OFF_DTB   = OFF_XBC   + SZ_XBC;
constexpr size_t OFF_CUM   = OFF_DTB   + SZ_DTB;
constexpr size_t OFF_CSUM  = OFF_CUM   + SZ_DTB;
constexpr size_t OFF_SLOC  = OFF_CSUM  + (size_t)NBATCH*NH*NCHUNK;
constexpr size_t OFF_SBEG  = OFF_SLOC  + SZ_SL;
constexpr size_t OFF_Y     = OFF_SBEG  + SZ_SL;
constexpr size_t OFF_KEYS  = OFF_Y     + SZ_Y;
constexpr size_t OFF_KPE   = OFF_KEYS  + SZ_XF;
constexpr size_t OFF_KEYSPE= OFF_KPE   + SZ_KPE;
constexpr size_t OFF_TK    = OFF_KEYSPE+ SZ_XF;
constexpr size_t OFF_TV    = OFF_TK    + SZ_I160;
constexpr size_t OFF_IQ    = OFF_TV    + SZ_I160;
constexpr size_t OFF_IATT  = OFF_IQ    + SZ_I160;
constexpr size_t OFF_ATT   = OFF_IATT  + SZ_I160;
constexpr size_t OFF_Q     = OFF_ATT   + SZ_ATT;
constexpr size_t OFF_QPE   = OFF_Q     + 3840;
constexpr size_t OFF_SQ    = OFF_QPE   + 3840;
constexpr size_t OFF_SK    = OFF_SQ    + 3840;
constexpr size_t OFF_SV    = OFF_SK    + 3840;
constexpr size_t OFF_SO    = OFF_SV    + 3840;
constexpr size_t OFF_QS160 = OFF_SO    + 3840;
constexpr size_t OFF_KS160 = OFF_QS160 + 1920;
constexpr size_t OFF_VS160 = OFF_KS160 + 1920;
constexpr size_t OFF_TATT  = OFF_VS160 + 1920;
constexpr size_t OFF_MLPH  = OFF_TATT  + 1920;
constexpr size_t ARENA_FLOATS = OFF_MLPH + 12288;

__device__ __align__(128) float g_arena[ARENA_FLOATS];

// ------------------------------ reduces ------------------------------
__device__ __forceinline__ float blockReduceSum(float v) {
    __shared__ float sh[33];
    int lane = threadIdx.x & 31, wid = threadIdx.x >> 5;
#pragma unroll
    for (int o = 16; o; o >>= 1) v += __shfl_down_sync(0xffffffffu, v, o);
    if (lane == 0) sh[wid] = v;
    __syncthreads();
    int nw = (blockDim.x + 31) >> 5;
    if (wid == 0) {
        v = (lane < nw) ? sh[lane] : 0.f;
#pragma unroll
        for (int o = 16; o; o >>= 1) v += __shfl_down_sync(0xffffffffu, v, o);
        if (lane == 0) sh[32] = v;
    }
    __syncthreads();
    v = sh[32];
    __syncthreads();
    return v;
}

__device__ __forceinline__ float blockReduceMax(float v) {
    __shared__ float sh[33];
    int lane = threadIdx.x & 31, wid = threadIdx.x >> 5;
#pragma unroll
    for (int o = 16; o; o >>= 1) v = fmaxf(v, __shfl_down_sync(0xffffffffu, v, o));
    if (lane == 0) sh[wid] = v;
    __syncthreads();
    int nw = (blockDim.x + 31) >> 5;
    if (wid == 0) {
        v = (lane < nw) ? sh[lane] : -1e30f;
#pragma unroll
        for (int o = 16; o; o >>= 1) v = fmaxf(v, __shfl_down_sync(0xffffffffu, v, o));
        if (lane == 0) sh[32] = v;
    }
    __syncthreads();
    v = sh[32];
    __syncthreads();
    return v;
}

__device__ __forceinline__ float siluf(float x) { return x / (1.f + expf(-x)); }

// ------------------------------ transposes ------------------------------
__global__ void k_transpose_in(const float* __restrict__ x, float* __restrict__ xf) {
    __shared__ float tile[32][33];
    int b = blockIdx.z;
    int t0 = blockIdx.x * 32, c0 = blockIdx.y * 32;
#pragma unroll
    for (int i = 0; i < 4; i++) {
        int cc = threadIdx.y + i * 8;
        tile[threadIdx.x][cc] = x[((size_t)(b * CDIM + c0 + cc)) * NTOK + t0 + threadIdx.x];
    }
    __syncthreads();
#pragma unroll
    for (int i = 0; i < 4; i++) {
        int tt = threadIdx.y + i * 8;
        xf[((size_t)(b * NTOK + t0 + tt)) * CDIM + c0 + threadIdx.x] = tile[tt][threadIdx.x];
    }
}

__global__ void k_transpose_out(const float* __restrict__ keys, float* __restrict__ out) {
    __shared__ float tile[32][33];
    int b = blockIdx.z;
    int t0 = blockIdx.x * 32, c0 = blockIdx.y * 32;
#pragma unroll
    for (int i = 0; i < 4; i++) {
        int tt = threadIdx.y + i * 8;
        tile[threadIdx.x][tt] = keys[((size_t)(b * NTOK + t0 + tt)) * CDIM + c0 + threadIdx.x];
    }
    __syncthreads();
#pragma unroll
    for (int i = 0; i < 4; i++) {
        int cc = threadIdx.y + i * 8;
        out[((size_t)(b * CDIM + c0 + cc)) * NTOK + t0 + threadIdx.x] = tile[cc][threadIdx.x];
    }
}

// ------------------------------ layernorm (blockDim == D) ------------------------------
__global__ void k_ln(const float* __restrict__ src, float* __restrict__ dst,
                     const float* __restrict__ w, const float* __restrict__ b) {
    int row = blockIdx.x;
    int D = blockDim.x;
    float v = src[(size_t)row * D + threadIdx.x];
    float m = blockReduceSum(v) / D;
    float d = v - m;
    float var = blockReduceSum(d * d) / D;
    dst[(size_t)row * D + threadIdx.x] = d * rsqrtf(var + 1e-5f) * w[threadIdx.x] + b[threadIdx.x];
}

// ------------------------------ GEMM: C = A(M,K) @ W(N,K)^T (+bias)(+R) ------------------------------
__global__ void k_gemm(const float* __restrict__ A, const float* __restrict__ W,
                       const float* __restrict__ bias, const float* __restrict__ R,
                       float* __restrict__ C, int M, int N, int K) {
    __shared__ float As[16][65];
    __shared__ float Bs[16][65];
    int tx = threadIdx.x, ty = threadIdx.y;
    int tid = ty * 16 + tx;
    int m0 = blockIdx.y * 64, n0 = blockIdx.x * 64;
    int ar = tid >> 2;
    int ac0 = (tid & 3) * 4;
    float acc[4][4] = {};
    for (int k0 = 0; k0 < K; k0 += 16) {
        float4 av = *(const float4*)&A[(size_t)(m0 + ar) * K + k0 + ac0];
        As[ac0 + 0][ar] = av.x; As[ac0 + 1][ar] = av.y;
        As[ac0 + 2][ar] = av.z; As[ac0 + 3][ar] = av.w;
        int n = n0 + ar;
        if (n < N) {
            float4 bv = *(const float4*)&W[(size_t)n * K + k0 + ac0];
            Bs[ac0 + 0][ar] = bv.x; Bs[ac0 + 1][ar] = bv.y;
            Bs[ac0 + 2][ar] = bv.z; Bs[ac0 + 3][ar] = bv.w;
        } else {
            Bs[ac0 + 0][ar] = 0.f; Bs[ac0 + 1][ar] = 0.f;
            Bs[ac0 + 2][ar] = 0.f; Bs[ac0 + 3][ar] = 0.f;
        }
        __syncthreads();
#pragma unroll
        for (int kk = 0; kk < 16; kk++) {
            float a[4], b[4];
#pragma unroll
            for (int i = 0; i < 4; i++) a[i] = As[kk][ty * 4 + i];
#pragma unroll
            for (int j = 0; j < 4; j++) b[j] = Bs[kk][tx * 4 + j];
#pragma unroll
            for (int i = 0; i < 4; i++)
#pragma unroll
                for (int j = 0; j < 4; j++) acc[i][j] += a[i] * b[j];
        }
        __syncthreads();
    }
#pragma unroll
    for (int i = 0; i < 4; i++) {
        int m = m0 + ty * 4 + i;
#pragma unroll
        for (int j = 0; j < 4; j++) {
            int n = n0 + tx * 4 + j;
            if (n < N) {
                float v = acc[i][j];
                if (bias) v += bias[n];
                if (R) v += R[(size_t)m * N + n];
                C[(size_t)m * N + n] = v;
            }
        }
    }
}

// ------------------------------ tiny GEMM for 12-row query ops ------------------------------
__global__ void k_tiny(const float* __restrict__ A1, const float* __restrict__ A2,
                       const float* __restrict__ W, const float* __restrict__ bias,
                       const float* __restrict__ R, float* __restrict__ C,
                       int N, int K, int act) {
    int r = blockIdx.y;
    int n = blockIdx.x * 64 + threadIdx.x;
    if (n >= N) return;
    const float* a1 = A1 + (size_t)r * K;
    const float* a2 = A2 ? A2 + (size_t)r * K : nullptr;
    const float* w = W + (size_t)n * K;
    float acc = bias ? bias[n] : 0.f;
    if (a2) { for (int k = 0; k < K; k++) acc += (a1[k] + a2[k]) * w[k]; }
    else    { for (int k = 0; k < K; k++) acc += a1[k] * w[k]; }
    if (act == 1) acc = fmaxf(acc, 0.f);
    if (R) acc += R[(size_t)r * N + n];
    C[(size_t)r * N + n] = acc;
}

// ------------------------------ conv + dt ------------------------------
__global__ void k_convdt(const float* __restrict__ zx, const float* __restrict__ conv_w,
                         const float* __restrict__ conv_b, const float* __restrict__ dt_bias,
                         float* __restrict__ xbc, float* __restrict__ dtb) {
    int b = blockIdx.x >> 14;
    int t = blockIdx.x & (NTOK - 1);
    int tid = threadIdx.x;
    for (int c = tid; c < CONVD; c += 256) {
        float acc = conv_b[c];
#pragma unroll
        for (int k = 0; k < 4; k++) {
            int ts = t + k - 3;
            float xv = (ts >= 0) ? zx[((size_t)(b * NTOK + ts)) * DIN + DINNER + c] : 0.f;
            acc += xv * conv_w[c * 4 + k];
        }
        xbc[((size_t)(b * NTOK + t)) * CONVD + c] = siluf(acc);
    }
    if (tid < NH) {
        float xv = zx[((size_t)(b * NTOK + t)) * DIN + DINNER + CONVD + tid] + dt_bias[tid];
        float dt = (xv > 20.f) ? xv : log1pf(expf(xv));
        dtb[(((size_t)(b * NH + tid)) << 14) + t] = dt;
    }
}

// ------------------------------ per-chunk cumsum ------------------------------
__global__ void k_cumsum(const float* __restrict__ dtb, const float* __restrict__ A_log,
                         float* __restrict__ cum, float* __restrict__ csum) {
    int bh = blockIdx.x;
    int h = bh & 7;
    float A = -expf(A_log[h]);
    int c = threadIdx.x;
    size_t base = ((size_t)bh << 14) + (size_t)c * 64;
    float run = 0.f;
    for (int t = 0; t < 64; t++) {
        run += dtb[base + t] * A;
        cum[base + t] = run;
    }
    csum[bh * NCHUNK + c] = run;
}

// ------------------------------ per-chunk local state ------------------------------
__global__ void k_chunkstate(const float* __restrict__ xbc, const float* __restrict__ cum,
                             const float* __restrict__ dtb, float* __restrict__ sloc) {
    int idx = blockIdx.x;
    int c = idx & 255, bh = idx >> 8;
    int b = bh >> 3, h = bh & 7;
    __shared__ float sB[64 * 32];
    __shared__ float sx[64 * 80];
    __shared__ float coef[64];
    int tid = threadIdx.x;
    size_t tbase = (size_t)b * NTOK + (size_t)c * 64;
    for (int e = tid; e < 64 * 32; e += 256) {
        int t = e >> 5, n = e & 31;
        sB[e] = xbc[(tbase + t) * CONVD + DINNER + n];
    }
    for (int e = tid; e < 64 * 80; e += 256) {
        int t = e / 80, p = e % 80;
        sx[e] = xbc[(tbase + t) * CONVD + h * HP + p];
    }
    if (tid < 64) {
        size_t cb = ((size_t)bh << 14) + (size_t)c * 64;
        float cl = cum[cb + 63];
        coef[tid] = expf(cl - cum[cb + tid]) * dtb[cb + tid];
    }
    __syncthreads();
    size_t obase = ((size_t)bh * NCHUNK + c) * 2560;
    for (int e = tid; e < 2560; e += 256) {
        int n = e / 80, p = e % 80;
        float acc = 0.f;
#pragma unroll 8
        for (int t = 0; t < 64; t++) acc += coef[t] * sB[t * 32 + n] * sx[t * 80 + p];
        sloc[obase + e] = acc;
    }
}

// ------------------------------ inter-chunk scan ------------------------------
__global__ void k_scan(const float* __restrict__ sloc, const float* __restrict__ csum,
                       float* __restrict__ sbeg) {
    int bh = blockIdx.x;
    int tid = threadIdx.x;
    float S[10];
#pragma unroll
    for (int k = 0; k < 10; k++) S[k] = 0.f;
    for (int c = 0; c < NCHUNK; c++) {
        size_t base = ((size_t)bh * NCHUNK + c) * 2560;
        float dec = expf(csum[bh * NCHUNK + c]);
#pragma unroll
        for (int k = 0; k < 10; k++) {
            sbeg[base + tid + k * 256] = S[k];
            S[k] = S[k] * dec + sloc[base + tid + k * 256];
        }
    }
}

// ------------------------------ per-chunk output ------------------------------
__global__ void k_chunkout(const float* __restrict__ xbc, const float* __restrict__ cum,
                           const float* __restrict__ dtb, const float* __restrict__ sbeg,
                           const float* __restrict__ Dp, float* __restrict__ y) {
    int idx = blockIdx.x;
    int c = idx & 255, bh = idx >> 8;
    int b = bh >> 3, h = bh & 7;
    __shared__ float sM[4096];
    __shared__ float sC[2048];
    __shared__ float sR[5120];
    __shared__ float sCum[64];
    __shared__ float sDt[64];
    int tid = threadIdx.x;
    size_t tbase = (size_t)b * NTOK + (size_t)c * 64;
    size_t cb = ((size_t)bh << 14) + (size_t)c * 64;
    size_t sb_base = ((size_t)bh * NCHUNK + c) * 2560;
    // phase A: begin-state contribution
    for (int e = tid; e < 2048; e += 256) {
        int t = e >> 5, n = e & 31;
        sC[e] = xbc[(tbase + t) * CONVD + DINNER + DSTATE + n];
    }
    for (int e = tid; e < 2560; e += 256) sR[e] = sbeg[sb_base + e];
    if (tid < 64) { sCum[tid] = cum[cb + tid]; sDt[tid] = dtb[cb + tid]; }
    __syncthreads();
    float acc[20];
#pragma unroll
    for (int k = 0; k < 20; k++) {
        int e = tid + k * 256;
        int t = e / 80, p = e % 80;
        float a = 0.f;
#pragma unroll 8
        for (int n = 0; n < 32; n++) a += sC[t * 32 + n] * sR[n * 80 + p];
        acc[k] = expf(sCum[t]) * a;
    }
    // phase B: decay-masked Gram matrix
    __syncthreads();
    for (int e = tid; e < 2048; e += 256) {
        int t = e >> 5, n = e & 31;
        sR[e] = xbc[(tbase + t) * CONVD + DINNER + n];  // B vectors
    }
    __syncthreads();
    for (int e = tid; e < 4096; e += 256) {
        int t = e >> 6, s = e & 63;
        float m = 0.f;
        if (s <= t) {
            float d = 0.f;
#pragma unroll 8
            for (int n = 0; n < 32; n++) d += sC[t * 32 + n] * sR[s * 32 + n];
            m = d * expf(sCum[t] - sCum[s]) * sDt[s];
        }
        sM[e] = m;
    }
    // phase C: intra-chunk output + D term
    __syncthreads();
    for (int e = tid; e < 5120; e += 256) {
        int t = e / 80, p = e % 80;
        sR[e] = xbc[(tbase + t) * CONVD + h * HP + p];  // x vectors
    }
    __syncthreads();
    float dph = Dp[h];
#pragma unroll
    for (int k = 0; k < 20; k++) {
        int e = tid + k * 256;
        int t = e / 80, p = e % 80;
        float a = acc[k];
        for (int s = 0; s < 64; s++) a += sM[t * 64 + s] * sR[s * 80 + p];
        a += dph * sR[t * 80 + p];
        y[(tbase + t) * DINNER + h * HP + p] = a;
    }
}

// ------------------------------ gate + rmsnorm (block 640) ------------------------------
__global__ void k_gaterms(float* __restrict__ y, const float* __restrict__ zx,
                          const float* __restrict__ rms_w) {
    size_t row = blockIdx.x;
    int e = threadIdx.x;
    float v = y[row * DINNER + e];
    float z = zx[row * DIN + e];
    v = v * siluf(z);
    float ms = blockReduceSum(v * v) / DINNER;
    y[row * DINNER + e] = v * rsqrtf(ms + 1e-5f) * rms_w[e];
}

// ------------------------------ positional encodings ------------------------------
__global__ void k_kpe(const float* __restrict__ gauss, float* __restrict__ kpe) {
    int t = blockIdx.x;
    int j = threadIdx.x;
    int d = t >> 10, hh = (t >> 5) & 31, w = t & 31;
    float g0 = 2.f * ((d + 0.5f) / 16.f) - 1.f;
    float g1 = 2.f * ((hh + 0.5f) / 32.f) - 1.f;
    float g2 = 2.f * ((w + 0.5f) / 32.f) - 1.f;
    float ang = 6.283185307179586f * (g0 * gauss[j] + g1 * gauss[160 + j] + g2 * gauss[320 + j]);
    kpe[(size_t)t * CDIM + j] = sinf(ang);
    kpe[(size_t)t * CDIM + 160 + j] = cosf(ang);
}

__global__ void k_pointemb(const float* __restrict__ coords, const int* __restrict__ labels,
                           const float* __restrict__ gauss, const float* __restrict__ ptab,
                           float* __restrict__ q, float* __restrict__ qpe) {
    int r = blockIdx.x;
    int j = threadIdx.x;
    float c0 = coords[r * 3 + 0] * (2.f / 128.f) - 1.f;
    float c1 = coords[r * 3 + 1] * (2.f / 256.f) - 1.f;
    float c2 = coords[r * 3 + 2] * (2.f / 256.f) - 1.f;
    float ang = 6.283185307179586f * (c0 * gauss[j] + c1 * gauss[160 + j] + c2 * gauss[320 + j]);
    int lab = labels[r];
    float s = sinf(ang) + ptab[lab * CDIM + j];
    float cc = cosf(ang) + ptab[lab * CDIM + 160 + j];
    q[r * CDIM + j] = s;      q[r * CDIM + 160 + j] = cc;
    qpe[r * CDIM + j] = s;    qpe[r * CDIM + 160 + j] = cc;
}

// ------------------------------ small self-attention (6 queries, 4 heads, hd=80) ------------------------------
__global__ void k_selfattn(const float* __restrict__ q, const float* __restrict__ k,
                           const float* __restrict__ v, float* __restrict__ o) {
    int b = blockIdx.x >> 2, h = blockIdx.x & 3;
    __shared__ float sc[6][6];
    int tid = threadIdx.x;
    if (tid < 36) {
        int qi = tid / 6, ki = tid % 6;
        float s = 0.f;
        for (int d = 0; d < 80; d++)
            s += q[(b * 6 + qi) * CDIM + h * 80 + d] * k[(b * 6 + ki) * CDIM + h * 80 + d];
        sc[qi][ki] = s * 0.11180339887498948f;  // 1/sqrt(80)
    }
    __syncthreads();
    if (tid < 6) {
        float mx = -1e30f;
        for (int j = 0; j < 6; j++) mx = fmaxf(mx, sc[tid][j]);
        float sum = 0.f;
        for (int j = 0; j < 6; j++) { float e = expf(sc[tid][j] - mx); sc[tid][j] = e; sum += e; }
        float inv = 1.f / sum;
        for (int j = 0; j < 6; j++) sc[tid][j] *= inv;
    }
    __syncthreads();
    for (int e = tid; e < 480; e += 128) {
        int qi = e / 80, d = e % 80;
        float a = 0.f;
        for (int j = 0; j < 6; j++) a += sc[qi][j] * v[(b * 6 + j) * CDIM + h * 80 + d];
        o[(b * 6 + qi) * CDIM + h * 80 + d] = a;
    }
}

// ------------------------------ t2i cross-attention (6 queries x 16384 keys) ------------------------------
__global__ void k_xscore(const float* __restrict__ q, const float* __restrict__ kimg,
                         float* __restrict__ att) {
    int r = blockIdx.x;
    int b = r / 24, h = (r % 24) / 6, qi = r % 6;
    __shared__ float sq[40];
    int tid = threadIdx.x;
    if (tid < 40) sq[tid] = q[(b * 6 + qi) * INNERD + h * 40 + tid];
    __syncthreads();
    int key = blockIdx.y * 256 + tid;
    const float* kr = kimg + ((size_t)b * NTOK + key) * INNERD + h * 40;
    float s = 0.f;
#pragma unroll
    for (int d = 0; d < 40; d++) s += sq[d] * kr[d];
    att[(size_t)r * NTOK + key] = s * 0.15811388300841897f;  // 1/sqrt(40)
}

__global__ void k_xsoftmax(float* __restrict__ att) {
    int r = blockIdx.x, tid = threadIdx.x;
    float* row = att + (size_t)r * NTOK;
    float mx = -1e30f;
    for (int i = tid; i < NTOK; i += 256) mx = fmaxf(mx, row[i]);
    mx = blockReduceMax(mx);
    float s = 0.f;
    for (int i = tid; i < NTOK; i += 256) s += expf(row[i] - mx);
    s = blockReduceSum(s);
    float inv = 1.f / s;
    for (int i = tid; i < NTOK; i += 256) row[i] = expf(row[i] - mx) * inv;
}

__global__ void k_xout(const float* __restrict__ att, const float* __restrict__ v,
                       float* __restrict__ o) {
    int r = blockIdx.x;
    int b = r / 24, h = (r % 24) / 6, qi = r % 6;
    int tid = threadIdx.x;
    float acc[40];
#pragma unroll
    for (int d = 0; d < 40; d++) acc[d] = 0.f;
    for (int key = tid; key < NTOK; key += 256) {
        float p = att[(size_t)r * NTOK + key];
        const float* vr = v + ((size_t)b * NTOK + key) * INNERD + h * 40;
#pragma unroll
        for (int d = 0; d < 40; d++) acc[d] += p * vr[d];
    }
    __shared__ float red[40 * 256];
#pragma unroll
    for (int d = 0; d < 40; d++) red[d * 256 + tid] = acc[d];
    __syncthreads();
    for (int s = 128; s > 0; s >>= 1) {
        if (tid < s)
#pragma unroll
            for (int d = 0; d < 40; d++) red[d * 256 + tid] += red[d * 256 + tid + s];
        __syncthreads();
    }
    if (tid < 40) o[(b * 6 + qi) * INNERD + h * 40 + tid] = red[tid * 256];
}

// ------------------------------ i2t attention (16384 img queries x 6 keys) ------------------------------
__global__ void k_i2t(const float* __restrict__ qimg, const float* __restrict__ ks,
                      const float* __restrict__ vs, float* __restrict__ o) {
    __shared__ float sk[960], sv[960];
    int b = blockIdx.y;
    int tid = threadIdx.x;
    for (int e = tid; e < 960; e += 128) { sk[e] = ks[b * 960 + e]; sv[e] = vs[b * 960 + e]; }
    __syncthreads();
    int tok = blockIdx.x * 32 + (tid >> 2);
    int h = tid & 3;
    const float* qrow = qimg + ((size_t)b * NTOK + tok) * INNERD + h * 40;
    float qv[40];
#pragma unroll
    for (int d = 0; d < 40; d++) qv[d] = qrow[d];
    float sc[6];
    float mx = -1e30f;
#pragma unroll
    for (int j = 0; j < 6; j++) {
        float s = 0.f;
#pragma unroll
        for (int d = 0; d < 40; d++) s += qv[d] * sk[j * INNERD + h * 40 + d];
        sc[j] = s * 0.15811388300841897f;
        mx = fmaxf(mx, sc[j]);
    }
    float sum = 0.f;
#pragma unroll
    for (int j = 0; j < 6; j++) { sc[j] = expf(sc[j] - mx); sum += sc[j]; }
    float inv = 1.f / sum;
    float* orow = o + ((size_t)b * NTOK + tok) * INNERD + h * 40;
#pragma unroll
    for (int d = 0; d < 40; d++) {
        float a = 0.f;
#pragma unroll
        for (int j = 0; j < 6; j++) a += sc[j] * sv[j * INNERD + h * 40 + d];
        orow[d] = a * inv;
    }
}

// ------------------------------ keys + kpe ------------------------------
__global__ void k_addpe(const float* __restrict__ keys, const float* __restrict__ kpe,
                        float* __restrict__ dst) {
    size_t i = (size_t)blockIdx.x * 256 + threadIdx.x;
    size_t total = SZ_XF;
    if (i < total) dst[i] = keys[i] + kpe[i % SZ_KPE];
}

// ------------------------------ host ------------------------------
extern "C" void kernel_launch(void* const* d_in, const int* in_sizes, int n_in,
                              void* d_out, int out_size) {
    const float* x        = (const float*)d_in[0];
    const float* coords   = (const float*)d_in[1];
    const int*   labels   = (const int*)  d_in[2];
    const float* ln_w     = (const float*)d_in[3];
    const float* ln_b     = (const float*)d_in[4];
    const float* in_w     = (const float*)d_in[5];
    const float* conv_w   = (const float*)d_in[6];
    const float* conv_b   = (const float*)d_in[7];
    const float* dt_bias  = (const float*)d_in[8];
    const float* A_log    = (const float*)d_in[9];
    const float* Dp       = (const float*)d_in[10];
    const float* rms_w    = (const float*)d_in[11];
    const float* out_w    = (const float*)d_in[12];
    const float* pe_gauss = (const float*)d_in[13];
    const float* point_tab= (const float*)d_in[14];
    const float* sa_w     = (const float*)d_in[15];
    const float* sa_b     = (const float*)d_in[16];
    const float* t2i_w    = (const float*)d_in[17];
    const float* t2i_b    = (const float*)d_in[18];
    const float* t2i_ow   = (const float*)d_in[19];
    const float* t2i_ob   = (const float*)d_in[20];
    const float* i2t_w    = (const float*)d_in[21];
    const float* i2t_b    = (const float*)d_in[22];
    const float* i2t_ow   = (const float*)d_in[23];
    const float* i2t_ob   = (const float*)d_in[24];
    const float* norms_w  = (const float*)d_in[25];
    const float* norms_b  = (const float*)d_in[26];
    const float* mlp_w1   = (const float*)d_in[27];
    const float* mlp_b1   = (const float*)d_in[28];
    const float* mlp_w2   = (const float*)d_in[29];
    const float* mlp_b2   = (const float*)d_in[30];
    float* out = (float*)d_out;

    float* ar = nullptr;
    cudaGetSymbolAddress((void**)&ar, g_arena);

    float* xf     = ar + OFF_XF;
    float* xn     = ar + OFF_XN;
    float* zx     = ar + OFF_ZX;
    float* xbc    = ar + OFF_XBC;
    float* dtb    = ar + OFF_DTB;
    float* cum    = ar + OFF_CUM;
    float* csum   = ar + OFF_CSUM;
    float* sloc   = ar + OFF_SLOC;
    float* sbeg   = ar + OFF_SBEG;
    float* ybuf   = ar + OFF_Y;
    float* keys   = ar + OFF_KEYS;
    float* kpe    = ar + OFF_KPE;
    float* keyspe = ar + OFF_KEYSPE;
    float* tk     = ar + OFF_TK;
    float* tv     = ar + OFF_TV;
    float* iq     = ar + OFF_IQ;
    float* iatt   = ar + OFF_IATT;
    float* att    = ar + OFF_ATT;
    float* queries= ar + OFF_Q;
    float* qpe    = ar + OFF_QPE;
    float* sq     = ar + OFF_SQ;
    float* sk     = ar + OFF_SK;
    float* sv     = ar + OFF_SV;
    float* so     = ar + OFF_SO;
    float* qs160  = ar + OFF_QS160;
    float* ks160  = ar + OFF_KS160;
    float* vs160  = ar + OFF_VS160;
    float* tatt   = ar + OFF_TATT;
    float* mlph   = ar + OFF_MLPH;

    const int MROWS = NBATCH * NTOK;  // 32768
    dim3 gb(16, 16);

    // ---- Mamba2 backbone ----
    k_transpose_in<<<dim3(NTOK / 32, CDIM / 32, NBATCH), dim3(32, 8)>>>(x, xf);
    k_ln<<<MROWS, CDIM>>>(xf, xn, ln_w, ln_b);
    k_gemm<<<dim3((DIN + 63) / 64, MROWS / 64), gb>>>(xn, in_w, nullptr, nullptr, zx, MROWS, DIN, CDIM);
    k_convdt<<<MROWS, 256>>>(zx, conv_w, conv_b, dt_bias, xbc, dtb);
    k_cumsum<<<NBATCH * NH, NCHUNK>>>(dtb, A_log, cum, csum);
    k_chunkstate<<<NBATCH * NH * NCHUNK, 256>>>(xbc, cum, dtb, sloc);
    k_scan<<<NBATCH * NH, 256>>>(sloc, csum, sbeg);
    k_chunkout<<<NBATCH * NH * NCHUNK, 256>>>(xbc, cum, dtb, sbeg, Dp, ybuf);
    k_gaterms<<<MROWS, DINNER>>>(ybuf, zx, rms_w);
    k_gemm<<<dim3((CDIM + 63) / 64, MROWS / 64), gb>>>(ybuf, out_w, nullptr, nullptr, keys, MROWS, CDIM, DINNER);

    // ---- positional encodings ----
    k_kpe<<<NTOK, 160>>>(pe_gauss, kpe);
    k_pointemb<<<12, 160>>>(coords, labels, pe_gauss, point_tab, queries, qpe);

    // ---- two transformer layers ----
    for (int i = 0; i < 2; i++) {
        const float* swq = sa_w + (size_t)(i * 4 + 0) * CDIM * CDIM;
        const float* swk = sa_w + (size_t)(i * 4 + 1) * CDIM * CDIM;
        const float* swv = sa_w + (size_t)(i * 4 + 2) * CDIM * CDIM;
        const float* swo = sa_w + (size_t)(i * 4 + 3) * CDIM * CDIM;
        const float* sbq = sa_b + (i * 4 + 0) * CDIM;
        const float* sbk = sa_b + (i * 4 + 1) * CDIM;
        const float* sbv = sa_b + (i * 4 + 2) * CDIM;
        const float* sbo = sa_b + (i * 4 + 3) * CDIM;

        // self-attention
        const float* pe_q = (i == 0) ? nullptr : qpe;
        k_tiny<<<dim3(5, 12), 64>>>(queries, pe_q, swq, sbq, nullptr, sq, CDIM, CDIM, 0);
        k_tiny<<<dim3(5, 12), 64>>>(queries, pe_q, swk, sbk, nullptr, sk, CDIM, CDIM, 0);
        k_tiny<<<dim3(5, 12), 64>>>(queries, nullptr, swv, sbv, nullptr, sv, CDIM, CDIM, 0);
        k_selfattn<<<8, 128>>>(sq, sk, sv, so);
        k_tiny<<<dim3(5, 12), 64>>>(so, nullptr, swo, sbo, (i == 0) ? nullptr : queries,
                                    queries, CDIM, CDIM, 0);
        k_ln<<<12, CDIM>>>(queries, queries, norms_w + (i * 4 + 0) * CDIM, norms_b + (i * 4 + 0) * CDIM);

        // keys + kpe for this layer
        k_addpe<<<(unsigned)((SZ_XF + 255) / 256), 256>>>(keys, kpe, keyspe);

        // t2i cross-attention
        k_tiny<<<dim3(3, 12), 64>>>(queries, qpe, t2i_w + (size_t)(i * 3 + 0) * INNERD * CDIM,
                                    t2i_b + (i * 3 + 0) * INNERD, nullptr, qs160, INNERD, CDIM, 0);
        k_gemm<<<dim3(3, MROWS / 64), gb>>>(keyspe, t2i_w + (size_t)(i * 3 + 1) * INNERD * CDIM,
                                            t2i_b + (i * 3 + 1) * INNERD, nullptr, tk, MROWS, INNERD, CDIM);
        k_gemm<<<dim3(3, MROWS / 64), gb>>>(keys, t2i_w + (size_t)(i * 3 + 2) * INNERD * CDIM,
                                            t2i_b + (i * 3 + 2) * INNERD, nullptr, tv, MROWS, INNERD, CDIM);
        k_xscore<<<dim3(48, 64), 256>>>(qs160, tk, att);
        k_xsoftmax<<<48, 256>>>(att);
        k_xout<<<48, 256>>>(att, tv, tatt);
        k_tiny<<<dim3(5, 12), 64>>>(tatt, nullptr, t2i_ow + (size_t)i * CDIM * INNERD,
                                    t2i_ob + i * CDIM, queries, queries, CDIM, INNERD, 0);
        k_ln<<<12, CDIM>>>(queries, queries, norms_w + (i * 4 + 1) * CDIM, norms_b + (i * 4 + 1) * CDIM);

        // MLP
        k_tiny<<<dim3(16, 12), 64>>>(queries, nullptr, mlp_w1 + (size_t)i * MLPD * CDIM,
                                     mlp_b1 + i * MLPD, nullptr, mlph, MLPD, CDIM, 1);
        k_tiny<<<dim3(5, 12), 64>>>(mlph, nullptr, mlp_w2 + (size_t)i * CDIM * MLPD,
                                    mlp_b2 + i * CDIM, queries, queries, CDIM, MLPD, 0);
        k_ln<<<12, CDIM>>>(queries, queries, norms_w + (i * 4 + 2) * CDIM, norms_b + (i * 4 + 2) * CDIM);

        // i2t cross-attention (image tokens attend to queries)
        k_gemm<<<dim3(3, MROWS / 64), gb>>>(keyspe, i2t_w + (size_t)(i * 3 + 0) * INNERD * CDIM,
                                            i2t_b + (i * 3 + 0) * INNERD, nullptr, iq, MROWS, INNERD, CDIM);
        k_tiny<<<dim3(3, 12), 64>>>(queries, qpe, i2t_w + (size_t)(i * 3 + 1) * INNERD * CDIM,
                                    i2t_b + (i * 3 + 1) * INNERD, nullptr, ks160, INNERD, CDIM, 0);
        k_tiny<<<dim3(3, 12), 64>>>(queries, nullptr, i2t_w + (size_t)(i * 3 + 2) * INNERD * CDIM,
                                    i2t_b + (i * 3 + 2) * INNERD, nullptr, vs160, INNERD, CDIM, 0);
        k_i2t<<<dim3(NTOK / 32, NBATCH), 128>>>(iq, ks160, vs160, iatt);
        k_gemm<<<dim3(5, MROWS / 64), gb>>>(iatt, i2t_ow + (size_t)i * CDIM * INNERD,
                                            i2t_ob + i * CDIM, keys, keys, MROWS, CDIM, INNERD);
        k_ln<<<MROWS, CDIM>>>(keys, keys, norms_w + (i * 4 + 3) * CDIM, norms_b + (i * 4 + 3) * CDIM);
    }

    // ---- output transpose ----
    k_transpose_out<<<dim3(NTOK / 32, CDIM / 32, NBATCH), dim3(32, 8)>>>(keys, out);
}

// round 3
// speedup vs baseline: 1.0751x; 1.0751x over previous
#include <cuda_runtime.h>
#include <math.h>
#include <stdint.h>

#define NBATCH 2
#define CDIM 320
#define NTOK 16384
#define DIN 1352
#define DINNER 640
#define CONVD 704
#define DSTATE 32
#define NH 8
#define HP 80
#define NCHUNK 256
#define INNERD 160
#define MLPD 1024

// ------------------------------ arena ------------------------------
constexpr size_t SZ_XF   = (size_t)NBATCH*NTOK*CDIM;
constexpr size_t SZ_ZX   = (size_t)NBATCH*NTOK*DIN;
constexpr size_t SZ_XBC  = (size_t)NBATCH*NTOK*CONVD;
constexpr size_t SZ_DTB  = (size_t)NBATCH*NH*NTOK;
constexpr size_t SZ_SL   = (size_t)NBATCH*NH*NCHUNK*DSTATE*HP;
constexpr size_t SZ_Y    = (size_t)NBATCH*NTOK*DINNER;
constexpr size_t SZ_KPE  = (size_t)NTOK*CDIM;
constexpr size_t SZ_I160 = (size_t)NBATCH*NTOK*INNERD;
constexpr size_t SZ_ATT  = (size_t)48*NTOK;

constexpr size_t OFF_XF    = 0;
constexpr size_t OFF_XN    = OFF_XF    + SZ_XF;
constexpr size_t OFF_ZX    = OFF_XN    + SZ_XF;
constexpr size_t OFF_XBC   = OFF_ZX    + SZ_ZX;
constexpr size_t OFF_DTB   = OFF_XBC   + SZ_XBC;
constexpr size_t OFF_CUM   = OFF_DTB   + SZ_DTB;
constexpr size_t OFF_CSUM  = OFF_CUM   + SZ_DTB;
constexpr size_t OFF_SLOC  = OFF_CSUM  + (size_t)NBATCH*NH*NCHUNK;
constexpr size_t OFF_SBEG  = OFF_SLOC  + SZ_SL;
constexpr size_t OFF_Y     = OFF_SBEG  + SZ_SL;
constexpr size_t OFF_KEYS  = OFF_Y     + SZ_Y;
constexpr size_t OFF_KPE   = OFF_KEYS  + SZ_XF;
constexpr size_t OFF_KEYSPE= OFF_KPE   + SZ_KPE;
constexpr size_t OFF_TK    = OFF_KEYSPE+ SZ_XF;
constexpr size_t OFF_TV    = OFF_TK    + SZ_I160;
constexpr size_t OFF_IQ    = OFF_TV    + SZ_I160;
constexpr size_t OFF_IATT  = OFF_IQ    + SZ_I160;
constexpr size_t OFF_ATT   = OFF_IATT  + SZ_I160;
constexpr size_t OFF_Q     = OFF_ATT   + SZ_ATT;
constexpr size_t OFF_QPE   = OFF_Q     + 3840;
constexpr size_t OFF_SQ    = OFF_QPE   + 3840;
constexpr size_t OFF_SK    = OFF_SQ    + 3840;
constexpr size_t OFF_SV    = OFF_SK    + 3840;
constexpr size_t OFF_SO    = OFF_SV    + 3840;
constexpr size_t OFF_QS160 = OFF_SO    + 3840;
constexpr size_t OFF_KS160 = OFF_QS160 + 1920;
constexpr size_t OFF_VS160 = OFF_KS160 + 1920;
constexpr size_t OFF_TATT  = OFF_VS160 + 1920;
constexpr size_t OFF_MLPH  = OFF_TATT  + 1920;
constexpr size_t ARENA_FLOATS = OFF_MLPH + 12288;

__device__ __align__(128) float g_arena[ARENA_FLOATS];

// ------------------------------ reduces ------------------------------
__device__ __forceinline__ float blockReduceSum(float v) {
    __shared__ float sh[33];
    int lane = threadIdx.x & 31, wid = threadIdx.x >> 5;
#pragma unroll
    for (int o = 16; o; o >>= 1) v += __shfl_down_sync(0xffffffffu, v, o);
    if (lane == 0) sh[wid] = v;
    __syncthreads();
    int nw = (blockDim.x + 31) >> 5;
    if (wid == 0) {
        v = (lane < nw) ? sh[lane] : 0.f;
#pragma unroll
        for (int o = 16; o; o >>= 1) v += __shfl_down_sync(0xffffffffu, v, o);
        if (lane == 0) sh[32] = v;
    }
    __syncthreads();
    v = sh[32];
    __syncthreads();
    return v;
}

__device__ __forceinline__ float blockReduceMax(float v) {
    __shared__ float sh[33];
    int lane = threadIdx.x & 31, wid = threadIdx.x >> 5;
#pragma unroll
    for (int o = 16; o; o >>= 1) v = fmaxf(v, __shfl_down_sync(0xffffffffu, v, o));
    if (lane == 0) sh[wid] = v;
    __syncthreads();
    int nw = (blockDim.x + 31) >> 5;
    if (wid == 0) {
        v = (lane < nw) ? sh[lane] : -1e30f;
#pragma unroll
        for (int o = 16; o; o >>= 1) v = fmaxf(v, __shfl_down_sync(0xffffffffu, v, o));
        if (lane == 0) sh[32] = v;
    }
    __syncthreads();
    v = sh[32];
    __syncthreads();
    return v;
}

__device__ __forceinline__ float siluf(float x) { return x / (1.f + expf(-x)); }

// ------------------------------ transposes ------------------------------
__global__ void k_transpose_in(const float* __restrict__ x, float* __restrict__ xf) {
    __shared__ float tile[32][33];
    int b = blockIdx.z;
    int t0 = blockIdx.x * 32, c0 = blockIdx.y * 32;
#pragma unroll
    for (int i = 0; i < 4; i++) {
        int cc = threadIdx.y + i * 8;
        tile[threadIdx.x][cc] = x[((size_t)(b * CDIM + c0 + cc)) * NTOK + t0 + threadIdx.x];
    }
    __syncthreads();
#pragma unroll
    for (int i = 0; i < 4; i++) {
        int tt = threadIdx.y + i * 8;
        xf[((size_t)(b * NTOK + t0 + tt)) * CDIM + c0 + threadIdx.x] = tile[tt][threadIdx.x];
    }
}

__global__ void k_transpose_out(const float* __restrict__ keys, float* __restrict__ out) {
    __shared__ float tile[32][33];
    int b = blockIdx.z;
    int t0 = blockIdx.x * 32, c0 = blockIdx.y * 32;
#pragma unroll
    for (int i = 0; i < 4; i++) {
        int tt = threadIdx.y + i * 8;
        tile[threadIdx.x][tt] = keys[((size_t)(b * NTOK + t0 + tt)) * CDIM + c0 + threadIdx.x];
    }
    __syncthreads();
#pragma unroll
    for (int i = 0; i < 4; i++) {
        int cc = threadIdx.y + i * 8;
        out[((size_t)(b * CDIM + c0 + cc)) * NTOK + t0 + threadIdx.x] = tile[cc][threadIdx.x];
    }
}

// ------------------------------ layernorm (blockDim == D) ------------------------------
__global__ void k_ln(const float* __restrict__ src, float* __restrict__ dst,
                     const float* __restrict__ w, const float* __restrict__ b) {
    int row = blockIdx.x;
    int D = blockDim.x;
    float v = src[(size_t)row * D + threadIdx.x];
    float m = blockReduceSum(v) / D;
    float d = v - m;
    float var = blockReduceSum(d * d) / D;
    dst[(size_t)row * D + threadIdx.x] = d * rsqrtf(var + 1e-5f) * w[threadIdx.x] + b[threadIdx.x];
}

// ------------------------------ GEMM: C = A(M,K) @ W(N,K)^T (+bias)(+R) ------------------------------
// BMxBN tile, 8x8 per thread, BK=8, double-buffered smem, vectorized.
// Requirements: M % BM == 0, K % 8 == 0, N % 4 == 0, pointers 16B-aligned.
template<int BM, int BN>
__global__ void __launch_bounds__((BM / 8) * (BN / 8))
k_gemm_t(const float* __restrict__ A, const float* __restrict__ W,
         const float* __restrict__ bias, const float* __restrict__ R,
         float* __restrict__ C, int M, int N, int K) {
    constexpr int T  = (BM / 8) * (BN / 8);
    constexpr int AL = BM * 2 / T;   // float4 A-loads per thread
    constexpr int BL = BN * 2 / T;   // float4 B-loads per thread
    __shared__ float As[2][8][BM];
    __shared__ float Bs[2][8][BN];

    const int tid = threadIdx.x;
    const int tx = tid % (BN / 8);
    const int ty = tid / (BN / 8);
    const int m0 = blockIdx.y * BM;
    const int n0 = blockIdx.x * BN;

    float4 rA[AL], rB[BL];

    auto loadG = [&](int k0) {
#pragma unroll
        for (int l = 0; l < AL; l++) {
            int idx = tid + l * T;
            int row = idx >> 1, c4 = (idx & 1) * 4;
            rA[l] = *(const float4*)&A[(size_t)(m0 + row) * K + k0 + c4];
        }
#pragma unroll
        for (int l = 0; l < BL; l++) {
            int idx = tid + l * T;
            int row = idx >> 1, c4 = (idx & 1) * 4;
            int n = n0 + row;
            rB[l] = (n < N) ? *(const float4*)&W[(size_t)n * K + k0 + c4]
                            : make_float4(0.f, 0.f, 0.f, 0.f);
        }
    };
    auto storeS = [&](int buf) {
#pragma unroll
        for (int l = 0; l < AL; l++) {
            int idx = tid + l * T;
            int row = idx >> 1, c4 = (idx & 1) * 4;
            As[buf][c4 + 0][row] = rA[l].x;
            As[buf][c4 + 1][row] = rA[l].y;
            As[buf][c4 + 2][row] = rA[l].z;
            As[buf][c4 + 3][row] = rA[l].w;
        }
#pragma unroll
        for (int l = 0; l < BL; l++) {
            int idx = tid + l * T;
            int row = idx >> 1, c4 = (idx & 1) * 4;
            Bs[buf][c4 + 0][row] = rB[l].x;
            Bs[buf][c4 + 1][row] = rB[l].y;
            Bs[buf][c4 + 2][row] = rB[l].z;
            Bs[buf][c4 + 3][row] = rB[l].w;
        }
    };

    float acc[8][8] = {};
    loadG(0);
    storeS(0);
    __syncthreads();

    int buf = 0;
    const int nk = K / 8;
    for (int t = 0; t < nk; t++) {
        if (t + 1 < nk) loadG((t + 1) * 8);
#pragma unroll
        for (int kk = 0; kk < 8; kk++) {
            float4 a0 = *(const float4*)&As[buf][kk][ty * 8];
            float4 a1 = *(const float4*)&As[buf][kk][ty * 8 + 4];
            float4 b0 = *(const float4*)&Bs[buf][kk][tx * 8];
            float4 b1 = *(const float4*)&Bs[buf][kk][tx * 8 + 4];
            float av[8] = {a0.x, a0.y, a0.z, a0.w, a1.x, a1.y, a1.z, a1.w};
            float bv[8] = {b0.x, b0.y, b0.z, b0.w, b1.x, b1.y, b1.z, b1.w};
#pragma unroll
            for (int i = 0; i < 8; i++)
#pragma unroll
                for (int j = 0; j < 8; j++) acc[i][j] += av[i] * bv[j];
        }
        if (t + 1 < nk) {
            storeS(buf ^ 1);
            __syncthreads();
            buf ^= 1;
        }
    }

#pragma unroll
    for (int i = 0; i < 8; i++) {
        size_t m = (size_t)(m0 + ty * 8 + i);
#pragma unroll
        for (int j = 0; j < 8; j += 4) {
            int n = n0 + tx * 8 + j;
            if (n < N) {
                float4 v = make_float4(acc[i][j], acc[i][j + 1], acc[i][j + 2], acc[i][j + 3]);
                if (bias) {
                    v.x += bias[n];     v.y += bias[n + 1];
                    v.z += bias[n + 2]; v.w += bias[n + 3];
                }
                if (R) {
                    float4 r = *(const float4*)&R[m * N + n];
                    v.x += r.x; v.y += r.y; v.z += r.z; v.w += r.w;
                }
                *(float4*)&C[m * N + n] = v;
            }
        }
    }
}

// ------------------------------ tiny GEMM for 12-row query ops ------------------------------
__global__ void k_tiny(const float* __restrict__ A1, const float* __restrict__ A2,
                       const float* __restrict__ W, const float* __restrict__ bias,
                       const float* __restrict__ R, float* __restrict__ C,
                       int N, int K, int act) {
    int r = blockIdx.y;
    int n = blockIdx.x * 64 + threadIdx.x;
    if (n >= N) return;
    const float* a1 = A1 + (size_t)r * K;
    const float* a2 = A2 ? A2 + (size_t)r * K : nullptr;
    const float* w = W + (size_t)n * K;
    float acc = bias ? bias[n] : 0.f;
    if (a2) { for (int k = 0; k < K; k++) acc += (a1[k] + a2[k]) * w[k]; }
    else    { for (int k = 0; k < K; k++) acc += a1[k] * w[k]; }
    if (act == 1) acc = fmaxf(acc, 0.f);
    if (R) acc += R[(size_t)r * N + n];
    C[(size_t)r * N + n] = acc;
}

// ------------------------------ conv + dt ------------------------------
__global__ void k_convdt(const float* __restrict__ zx, const float* __restrict__ conv_w,
                         const float* __restrict__ conv_b, const float* __restrict__ dt_bias,
                         float* __restrict__ xbc, float* __restrict__ dtb) {
    int b = blockIdx.x >> 14;
    int t = blockIdx.x & (NTOK - 1);
    int tid = threadIdx.x;
    for (int c = tid; c < CONVD; c += 256) {
        float acc = conv_b[c];
#pragma unroll
        for (int k = 0; k < 4; k++) {
            int ts = t + k - 3;
            float xv = (ts >= 0) ? zx[((size_t)(b * NTOK + ts)) * DIN + DINNER + c] : 0.f;
            acc += xv * conv_w[c * 4 + k];
        }
        xbc[((size_t)(b * NTOK + t)) * CONVD + c] = siluf(acc);
    }
    if (tid < NH) {
        float xv = zx[((size_t)(b * NTOK + t)) * DIN + DINNER + CONVD + tid] + dt_bias[tid];
        float dt = (xv > 20.f) ? xv : log1pf(expf(xv));
        dtb[(((size_t)(b * NH + tid)) << 14) + t] = dt;
    }
}

// ------------------------------ per-chunk cumsum ------------------------------
__global__ void k_cumsum(const float* __restrict__ dtb, const float* __restrict__ A_log,
                         float* __restrict__ cum, float* __restrict__ csum) {
    int bh = blockIdx.x;
    int h = bh & 7;
    float A = -expf(A_log[h]);
    int c = threadIdx.x;
    size_t base = ((size_t)bh << 14) + (size_t)c * 64;
    float run = 0.f;
    for (int t = 0; t < 64; t++) {
        run += dtb[base + t] * A;
        cum[base + t] = run;
    }
    csum[bh * NCHUNK + c] = run;
}

// ------------------------------ per-chunk local state ------------------------------
__global__ void k_chunkstate(const float* __restrict__ xbc, const float* __restrict__ cum,
                             const float* __restrict__ dtb, float* __restrict__ sloc) {
    int idx = blockIdx.x;
    int c = idx & 255, bh = idx >> 8;
    int b = bh >> 3, h = bh & 7;
    __shared__ float sB[64 * 32];
    __shared__ float sx[64 * 80];
    __shared__ float coef[64];
    int tid = threadIdx.x;
    size_t tbase = (size_t)b * NTOK + (size_t)c * 64;
    for (int e = tid; e < 64 * 32; e += 256) {
        int t = e >> 5, n = e & 31;
        sB[e] = xbc[(tbase + t) * CONVD + DINNER + n];
    }
    for (int e = tid; e < 64 * 80; e += 256) {
        int t = e / 80, p = e % 80;
        sx[e] = xbc[(tbase + t) * CONVD + h * HP + p];
    }
    if (tid < 64) {
        size_t cb = ((size_t)bh << 14) + (size_t)c * 64;
        float cl = cum[cb + 63];
        coef[tid] = expf(cl - cum[cb + tid]) * dtb[cb + tid];
    }
    __syncthreads();
    size_t obase = ((size_t)bh * NCHUNK + c) * 2560;
    for (int e = tid; e < 2560; e += 256) {
        int n = e / 80, p = e % 80;
        float acc = 0.f;
#pragma unroll 8
        for (int t = 0; t < 64; t++) acc += coef[t] * sB[t * 32 + n] * sx[t * 80 + p];
        sloc[obase + e] = acc;
    }
}

// ------------------------------ inter-chunk scan ------------------------------
__global__ void k_scan(const float* __restrict__ sloc, const float* __restrict__ csum,
                       float* __restrict__ sbeg) {
    int bh = blockIdx.x;
    int tid = threadIdx.x;
    float S[10];
#pragma unroll
    for (int k = 0; k < 10; k++) S[k] = 0.f;
    for (int c = 0; c < NCHUNK; c++) {
        size_t base = ((size_t)bh * NCHUNK + c) * 2560;
        float dec = expf(csum[bh * NCHUNK + c]);
#pragma unroll
        for (int k = 0; k < 10; k++) {
            sbeg[base + tid + k * 256] = S[k];
            S[k] = S[k] * dec + sloc[base + tid + k * 256];
        }
    }
}

// ------------------------------ per-chunk output ------------------------------
__global__ void k_chunkout(const float* __restrict__ xbc, const float* __restrict__ cum,
                           const float* __restrict__ dtb, const float* __restrict__ sbeg,
                           const float* __restrict__ Dp, float* __restrict__ y) {
    int idx = blockIdx.x;
    int c = idx & 255, bh = idx >> 8;
    int b = bh >> 3, h = bh & 7;
    __shared__ float sM[4096];
    __shared__ float sC[2048];
    __shared__ float sR[5120];
    __shared__ float sCum[64];
    __shared__ float sDt[64];
    int tid = threadIdx.x;
    size_t tbase = (size_t)b * NTOK + (size_t)c * 64;
    size_t cb = ((size_t)bh << 14) + (size_t)c * 64;
    size_t sb_base = ((size_t)bh * NCHUNK + c) * 2560;
    for (int e = tid; e < 2048; e += 256) {
        int t = e >> 5, n = e & 31;
        sC[e] = xbc[(tbase + t) * CONVD + DINNER + DSTATE + n];
    }
    for (int e = tid; e < 2560; e += 256) sR[e] = sbeg[sb_base + e];
    if (tid < 64) { sCum[tid] = cum[cb + tid]; sDt[tid] = dtb[cb + tid]; }
    __syncthreads();
    float acc[20];
#pragma unroll
    for (int k = 0; k < 20; k++) {
        int e = tid + k * 256;
        int t = e / 80, p = e % 80;
        float a = 0.f;
#pragma unroll 8
        for (int n = 0; n < 32; n++) a += sC[t * 32 + n] * sR[n * 80 + p];
        acc[k] = expf(sCum[t]) * a;
    }
    __syncthreads();
    for (int e = tid; e < 2048; e += 256) {
        int t = e >> 5, n = e & 31;
        sR[e] = xbc[(tbase + t) * CONVD + DINNER + n];
    }
    __syncthreads();
    for (int e = tid; e < 4096; e += 256) {
        int t = e >> 6, s = e & 63;
        float m = 0.f;
        if (s <= t) {
            float d = 0.f;
#pragma unroll 8
            for (int n = 0; n < 32; n++) d += sC[t * 32 + n] * sR[s * 32 + n];
            m = d * expf(sCum[t] - sCum[s]) * sDt[s];
        }
        sM[e] = m;
    }
    __syncthreads();
    for (int e = tid; e < 5120; e += 256) {
        int t = e / 80, p = e % 80;
        sR[e] = xbc[(tbase + t) * CONVD + h * HP + p];
    }
    __syncthreads();
    float dph = Dp[h];
#pragma unroll
    for (int k = 0; k < 20; k++) {
        int e = tid + k * 256;
        int t = e / 80, p = e % 80;
        float a = acc[k];
        for (int s = 0; s < 64; s++) a += sM[t * 64 + s] * sR[s * 80 + p];
        a += dph * sR[t * 80 + p];
        y[(tbase + t) * DINNER + h * HP + p] = a;
    }
}

// ------------------------------ gate + rmsnorm (block 640) ------------------------------
__global__ void k_gaterms(float* __restrict__ y, const float* __restrict__ zx,
                          const float* __restrict__ rms_w) {
    size_t row = blockIdx.x;
    int e = threadIdx.x;
    float v = y[row * DINNER + e];
    float z = zx[row * DIN + e];
    v = v * siluf(z);
    float ms = blockReduceSum(v * v) / DINNER;
    y[row * DINNER + e] = v * rsqrtf(ms + 1e-5f) * rms_w[e];
}

// ------------------------------ positional encodings ------------------------------
__global__ void k_kpe(const float* __restrict__ gauss, float* __restrict__ kpe) {
    int t = blockIdx.x;
    int j = threadIdx.x;
    int d = t >> 10, hh = (t >> 5) & 31, w = t & 31;
    float g0 = 2.f * ((d + 0.5f) / 16.f) - 1.f;
    float g1 = 2.f * ((hh + 0.5f) / 32.f) - 1.f;
    float g2 = 2.f * ((w + 0.5f) / 32.f) - 1.f;
    float ang = 6.283185307179586f * (g0 * gauss[j] + g1 * gauss[160 + j] + g2 * gauss[320 + j]);
    kpe[(size_t)t * CDIM + j] = sinf(ang);
    kpe[(size_t)t * CDIM + 160 + j] = cosf(ang);
}

__global__ void k_pointemb(const float* __restrict__ coords, const int* __restrict__ labels,
                           const float* __restrict__ gauss, const float* __restrict__ ptab,
                           float* __restrict__ q, float* __restrict__ qpe) {
    int r = blockIdx.x;
    int j = threadIdx.x;
    float c0 = coords[r * 3 + 0] * (2.f / 128.f) - 1.f;
    float c1 = coords[r * 3 + 1] * (2.f / 256.f) - 1.f;
    float c2 = coords[r * 3 + 2] * (2.f / 256.f) - 1.f;
    float ang = 6.283185307179586f * (c0 * gauss[j] + c1 * gauss[160 + j] + c2 * gauss[320 + j]);
    int lab = labels[r];
    float s = sinf(ang) + ptab[lab * CDIM + j];
    float cc = cosf(ang) + ptab[lab * CDIM + 160 + j];
    q[r * CDIM + j] = s;      q[r * CDIM + 160 + j] = cc;
    qpe[r * CDIM + j] = s;    qpe[r * CDIM + 160 + j] = cc;
}

// ------------------------------ small self-attention ------------------------------
__global__ void k_selfattn(const float* __restrict__ q, const float* __restrict__ k,
                           const float* __restrict__ v, float* __restrict__ o) {
    int b = blockIdx.x >> 2, h = blockIdx.x & 3;
    __shared__ float sc[6][6];
    int tid = threadIdx.x;
    if (tid < 36) {
        int qi = tid / 6, ki = tid % 6;
        float s = 0.f;
        for (int d = 0; d < 80; d++)
            s += q[(b * 6 + qi) * CDIM + h * 80 + d] * k[(b * 6 + ki) * CDIM + h * 80 + d];
        sc[qi][ki] = s * 0.11180339887498948f;
    }
    __syncthreads();
    if (tid < 6) {
        float mx = -1e30f;
        for (int j = 0; j < 6; j++) mx = fmaxf(mx, sc[tid][j]);
        float sum = 0.f;
        for (int j = 0; j < 6; j++) { float e = expf(sc[tid][j] - mx); sc[tid][j] = e; sum += e; }
        float inv = 1.f / sum;
        for (int j = 0; j < 6; j++) sc[tid][j] *= inv;
    }
    __syncthreads();
    for (int e = tid; e < 480; e += 128) {
        int qi = e / 80, d = e % 80;
        float a = 0.f;
        for (int j = 0; j < 6; j++) a += sc[qi][j] * v[(b * 6 + j) * CDIM + h * 80 + d];
        o[(b * 6 + qi) * CDIM + h * 80 + d] = a;
    }
}

// ------------------------------ t2i cross-attention ------------------------------
__global__ void k_xscore(const float* __restrict__ q, const float* __restrict__ kimg,
                         float* __restrict__ att) {
    int r = blockIdx.x;
    int b = r / 24, h = (r % 24) / 6, qi = r % 6;
    __shared__ float sq[40];
    int tid = threadIdx.x;
    if (tid < 40) sq[tid] = q[(b * 6 + qi) * INNERD + h * 40 + tid];
    __syncthreads();
    int key = blockIdx.y * 256 + tid;
    const float* kr = kimg + ((size_t)b * NTOK + key) * INNERD + h * 40;
    float s = 0.f;
#pragma unroll
    for (int d = 0; d < 40; d++) s += sq[d] * kr[d];
    att[(size_t)r * NTOK + key] = s * 0.15811388300841897f;
}

__global__ void k_xsoftmax(float* __restrict__ att) {
    int r = blockIdx.x, tid = threadIdx.x;
    float* row = att + (size_t)r * NTOK;
    float mx = -1e30f;
    for (int i = tid; i < NTOK; i += 256) mx = fmaxf(mx, row[i]);
    mx = blockReduceMax(mx);
    float s = 0.f;
    for (int i = tid; i < NTOK; i += 256) s += expf(row[i] - mx);
    s = blockReduceSum(s);
    float inv = 1.f / s;
    for (int i = tid; i < NTOK; i += 256) row[i] = expf(row[i] - mx) * inv;
}

__global__ void k_xout(const float* __restrict__ att, const float* __restrict__ v,
                       float* __restrict__ o) {
    int r = blockIdx.x;
    int b = r / 24, h = (r % 24) / 6, qi = r % 6;
    int tid = threadIdx.x;
    float acc[40];
#pragma unroll
    for (int d = 0; d < 40; d++) acc[d] = 0.f;
    for (int key = tid; key < NTOK; key += 256) {
        float p = att[(size_t)r * NTOK + key];
        const float* vr = v + ((size_t)b * NTOK + key) * INNERD + h * 40;
#pragma unroll
        for (int d = 0; d < 40; d++) acc[d] += p * vr[d];
    }
    __shared__ float red[40 * 256];
#pragma unroll
    for (int d = 0; d < 40; d++) red[d * 256 + tid] = acc[d];
    __syncthreads();
    for (int s = 128; s > 0; s >>= 1) {
        if (tid < s)
#pragma unroll
            for (int d = 0; d < 40; d++) red[d * 256 + tid] += red[d * 256 + tid + s];
        __syncthreads();
    }
    if (tid < 40) o[(b * 6 + qi) * INNERD + h * 40 + tid] = red[tid * 256];
}

// ------------------------------ i2t attention ------------------------------
__global__ void k_i2t(const float* __restrict__ qimg, const float* __restrict__ ks,
                      const float* __restrict__ vs, float* __restrict__ o) {
    __shared__ float sk[960], sv[960];
    int b = blockIdx.y;
    int tid = threadIdx.x;
    for (int e = tid; e < 960; e += 128) { sk[e] = ks[b * 960 + e]; sv[e] = vs[b * 960 + e]; }
    __syncthreads();
    int tok = blockIdx.x * 32 + (tid >> 2);
    int h = tid & 3;
    const float* qrow = qimg + ((size_t)b * NTOK + tok) * INNERD + h * 40;
    float qv[40];
#pragma unroll
    for (int d = 0; d < 40; d++) qv[d] = qrow[d];
    float sc[6];
    float mx = -1e30f;
#pragma unroll
    for (int j = 0; j < 6; j++) {
        float s = 0.f;
#pragma unroll
        for (int d = 0; d < 40; d++) s += qv[d] * sk[j * INNERD + h * 40 + d];
        sc[j] = s * 0.15811388300841897f;
        mx = fmaxf(mx, sc[j]);
    }
    float sum = 0.f;
#pragma unroll
    for (int j = 0; j < 6; j++) { sc[j] = expf(sc[j] - mx); sum += sc[j]; }
    float inv = 1.f / sum;
    float* orow = o + ((size_t)b * NTOK + tok) * INNERD + h * 40;
#pragma unroll
    for (int d = 0; d < 40; d++) {
        float a = 0.f;
#pragma unroll
        for (int j = 0; j < 6; j++) a += sc[j] * sv[j * INNERD + h * 40 + d];
        orow[d] = a * inv;
    }
}

// ------------------------------ keys + kpe ------------------------------
__global__ void k_addpe(const float* __restrict__ keys, const float* __restrict__ kpe,
                        float* __restrict__ dst) {
    size_t i = (size_t)blockIdx.x * 256 + threadIdx.x;
    size_t total = SZ_XF;
    if (i < total) dst[i] = keys[i] + kpe[i % SZ_KPE];
}

// ------------------------------ host ------------------------------
extern "C" void kernel_launch(void* const* d_in, const int* in_sizes, int n_in,
                              void* d_out, int out_size) {
    const float* x        = (const float*)d_in[0];
    const float* coords   = (const float*)d_in[1];
    const int*   labels   = (const int*)  d_in[2];
    const float* ln_w     = (const float*)d_in[3];
    const float* ln_b     = (const float*)d_in[4];
    const float* in_w     = (const float*)d_in[5];
    const float* conv_w   = (const float*)d_in[6];
    const float* conv_b   = (const float*)d_in[7];
    const float* dt_bias  = (const float*)d_in[8];
    const float* A_log    = (const float*)d_in[9];
    const float* Dp       = (const float*)d_in[10];
    const float* rms_w    = (const float*)d_in[11];
    const float* out_w    = (const float*)d_in[12];
    const float* pe_gauss = (const float*)d_in[13];
    const float* point_tab= (const float*)d_in[14];
    const float* sa_w     = (const float*)d_in[15];
    const float* sa_b     = (const float*)d_in[16];
    const float* t2i_w    = (const float*)d_in[17];
    const float* t2i_b    = (const float*)d_in[18];
    const float* t2i_ow   = (const float*)d_in[19];
    const float* t2i_ob   = (const float*)d_in[20];
    const float* i2t_w    = (const float*)d_in[21];
    const float* i2t_b    = (const float*)d_in[22];
    const float* i2t_ow   = (const float*)d_in[23];
    const float* i2t_ob   = (const float*)d_in[24];
    const float* norms_w  = (const float*)d_in[25];
    const float* norms_b  = (const float*)d_in[26];
    const float* mlp_w1   = (const float*)d_in[27];
    const float* mlp_b1   = (const float*)d_in[28];
    const float* mlp_w2   = (const float*)d_in[29];
    const float* mlp_b2   = (const float*)d_in[30];
    float* out = (float*)d_out;

    float* ar = nullptr;
    cudaGetSymbolAddress((void**)&ar, g_arena);

    float* xf     = ar + OFF_XF;
    float* xn     = ar + OFF_XN;
    float* zx     = ar + OFF_ZX;
    float* xbc    = ar + OFF_XBC;
    float* dtb    = ar + OFF_DTB;
    float* cum    = ar + OFF_CUM;
    float* csum   = ar + OFF_CSUM;
    float* sloc   = ar + OFF_SLOC;
    float* sbeg   = ar + OFF_SBEG;
    float* ybuf   = ar + OFF_Y;
    float* keys   = ar + OFF_KEYS;
    float* kpe    = ar + OFF_KPE;
    float* keyspe = ar + OFF_KEYSPE;
    float* tk     = ar + OFF_TK;
    float* tv     = ar + OFF_TV;
    float* iq     = ar + OFF_IQ;
    float* iatt   = ar + OFF_IATT;
    float* att    = ar + OFF_ATT;
    float* queries= ar + OFF_Q;
    float* qpe    = ar + OFF_QPE;
    float* sq     = ar + OFF_SQ;
    float* sk     = ar + OFF_SK;
    float* sv     = ar + OFF_SV;
    float* so     = ar + OFF_SO;
    float* qs160  = ar + OFF_QS160;
    float* ks160  = ar + OFF_KS160;
    float* vs160  = ar + OFF_VS160;
    float* tatt   = ar + OFF_TATT;
    float* mlph   = ar + OFF_MLPH;

    const int MROWS = NBATCH * NTOK;  // 32768

    // ---- Mamba2 backbone ----
    k_transpose_in<<<dim3(NTOK / 32, CDIM / 32, NBATCH), dim3(32, 8)>>>(x, xf);
    k_ln<<<MROWS, CDIM>>>(xf, xn, ln_w, ln_b);
    k_gemm_t<128, 128><<<dim3((DIN + 127) / 128, MROWS / 128), 256>>>(
        xn, in_w, nullptr, nullptr, zx, MROWS, DIN, CDIM);
    k_convdt<<<MROWS, 256>>>(zx, conv_w, conv_b, dt_bias, xbc, dtb);
    k_cumsum<<<NBATCH * NH, NCHUNK>>>(dtb, A_log, cum, csum);
    k_chunkstate<<<NBATCH * NH * NCHUNK, 256>>>(xbc, cum, dtb, sloc);
    k_scan<<<NBATCH * NH, 256>>>(sloc, csum, sbeg);
    k_chunkout<<<NBATCH * NH * NCHUNK, 256>>>(xbc, cum, dtb, sbeg, Dp, ybuf);
    k_gaterms<<<MROWS, DINNER>>>(ybuf, zx, rms_w);
    k_gemm_t<128, 64><<<dim3(CDIM / 64, MROWS / 128), 128>>>(
        ybuf, out_w, nullptr, nullptr, keys, MROWS, CDIM, DINNER);

    // ---- positional encodings ----
    k_kpe<<<NTOK, 160>>>(pe_gauss, kpe);
    k_pointemb<<<12, 160>>>(coords, labels, pe_gauss, point_tab, queries, qpe);

    // ---- two transformer layers ----
    for (int i = 0; i < 2; i++) {
        const float* swq = sa_w + (size_t)(i * 4 + 0) * CDIM * CDIM;
        const float* swk = sa_w + (size_t)(i * 4 + 1) * CDIM * CDIM;
        const float* swv = sa_w + (size_t)(i * 4 + 2) * CDIM * CDIM;
        const float* swo = sa_w + (size_t)(i * 4 + 3) * CDIM * CDIM;
        const float* sbq = sa_b + (i * 4 + 0) * CDIM;
        const float* sbk = sa_b + (i * 4 + 1) * CDIM;
        const float* sbv = sa_b + (i * 4 + 2) * CDIM;
        const float* sbo = sa_b + (i * 4 + 3) * CDIM;

        // self-attention
        const float* pe_q = (i == 0) ? nullptr : qpe;
        k_tiny<<<dim3(5, 12), 64>>>(queries, pe_q, swq, sbq, nullptr, sq, CDIM, CDIM, 0);
        k_tiny<<<dim3(5, 12), 64>>>(queries, pe_q, swk, sbk, nullptr, sk, CDIM, CDIM, 0);
        k_tiny<<<dim3(5, 12), 64>>>(queries, nullptr, swv, sbv, nullptr, sv, CDIM, CDIM, 0);
        k_selfattn<<<8, 128>>>(sq, sk, sv, so);
        k_tiny<<<dim3(5, 12), 64>>>(so, nullptr, swo, sbo, (i == 0) ? nullptr : queries,
                                    queries, CDIM, CDIM, 0);
        k_ln<<<12, CDIM>>>(queries, queries, norms_w + (i * 4 + 0) * CDIM, norms_b + (i * 4 + 0) * CDIM);

        // keys + kpe for this layer
        k_addpe<<<(unsigned)((SZ_XF + 255) / 256), 256>>>(keys, kpe, keyspe);

        // t2i cross-attention
        k_tiny<<<dim3(3, 12), 64>>>(queries, qpe, t2i_w + (size_t)(i * 3 + 0) * INNERD * CDIM,
                                    t2i_b + (i * 3 + 0) * INNERD, nullptr, qs160, INNERD, CDIM, 0);
        k_gemm_t<128, 64><<<dim3((INNERD + 63) / 64, MROWS / 128), 128>>>(
            keyspe, t2i_w + (size_t)(i * 3 + 1) * INNERD * CDIM,
            t2i_b + (i * 3 + 1) * INNERD, nullptr, tk, MROWS, INNERD, CDIM);
        k_gemm_t<128, 64><<<dim3((INNERD + 63) / 64, MROWS / 128), 128>>>(
            keys, t2i_w + (size_t)(i * 3 + 2) * INNERD * CDIM,
            t2i_b + (i * 3 + 2) * INNERD, nullptr, tv, MROWS, INNERD, CDIM);
        k_xscore<<<dim3(48, 64), 256>>>(qs160, tk, att);
        k_xsoftmax<<<48, 256>>>(att);
        k_xout<<<48, 256>>>(att, tv, tatt);
        k_tiny<<<dim3(5, 12), 64>>>(tatt, nullptr, t2i_ow + (size_t)i * CDIM * INNERD,
                                    t2i_ob + i * CDIM, queries, queries, CDIM, INNERD, 0);
        k_ln<<<12, CDIM>>>(queries, queries, norms_w + (i * 4 + 1) * CDIM, norms_b + (i * 4 + 1) * CDIM);

        // MLP
        k_tiny<<<dim3(16, 12), 64>>>(queries, nullptr, mlp_w1 + (size_t)i * MLPD * CDIM,
                                     mlp_b1 + i * MLPD, nullptr, mlph, MLPD, CDIM, 1);
        k_tiny<<<dim3(5, 12), 64>>>(mlph, nullptr, mlp_w2 + (size_t)i * CDIM * MLPD,
                                    mlp_b2 + i * CDIM, queries, queries, CDIM, MLPD, 0);
        k_ln<<<12, CDIM>>>(queries, queries, norms_w + (i * 4 + 2) * CDIM, norms_b + (i * 4 + 2) * CDIM);

        // i2t cross-attention
        k_gemm_t<128, 64><<<dim3((INNERD + 63) / 64, MROWS / 128), 128>>>(
            keyspe, i2t_w + (size_t)(i * 3 + 0) * INNERD * CDIM,
            i2t_b + (i * 3 + 0) * INNERD, nullptr, iq, MROWS, INNERD, CDIM);
        k_tiny<<<dim3(3, 12), 64>>>(queries, qpe, i2t_w + (size_t)(i * 3 + 1) * INNERD * CDIM,
                                    i2t_b + (i * 3 + 1) * INNERD, nullptr, ks160, INNERD, CDIM, 0);
        k_tiny<<<dim3(3, 12), 64>>>(queries, nullptr, i2t_w + (size_t)(i * 3 + 2) * INNERD * CDIM,
                                    i2t_b + (i * 3 + 2) * INNERD, nullptr, vs160, INNERD, CDIM, 0);
        k_i2t<<<dim3(NTOK / 32, NBATCH), 128>>>(iq, ks160, vs160, iatt);
        k_gemm_t<128, 64><<<dim3(CDIM / 64, MROWS / 128), 128>>>(
            iatt, i2t_ow + (size_t)i * CDIM * INNERD,
            i2t_ob + i * CDIM, keys, keys, MROWS, CDIM, INNERD);
        k_ln<<<MROWS, CDIM>>>(keys, keys, norms_w + (i * 4 + 3) * CDIM, norms_b + (i * 4 + 3) * CDIM);
    }

    // ---- output transpose ----
    k_transpose_out<<<dim3(NTOK / 32, CDIM / 32, NBATCH), dim3(32, 8)>>>(keys, out);
}